// round 1
// baseline (speedup 1.0000x reference)
#include <cuda_runtime.h>
#include <math.h>

#define B_SZ   8
#define T_LEN  64
#define NODES  325
#define DM     64
#define DI     128
#define DS     16
#define TOPK   8
#define EPSV   1e-5f
#define BN     (B_SZ*NODES)

// ------------------------- device scratch -------------------------
__device__ float g_xt[(size_t)BN*T_LEN*DM];              // (b,n,t,c)
__device__ float g_K [(size_t)B_SZ*T_LEN*NODES*DM];      // (b,t,n,c)
__device__ float g_V [(size_t)B_SZ*T_LEN*NODES*DM];      // (b,t,n,c)

__device__ __forceinline__ float siluf(float v){ return v / (1.f + __expf(-v)); }
__device__ __forceinline__ float softplusf(float v){ return v > 20.f ? v : log1pf(__expf(v)); }

// ---------------- kernel 1: mamba + residual + K/V proj ----------------
// smem layout (float offsets)
#define S_W    0          // 16448 : in_proj^T padded (64 x 257); later reused
#define S_H    16448      // 4096  : raw x -> layernormed x -> final xt rows
#define S_XC   20544      // 8192  : xi -> conv/silu -> y
#define S_Z    28736      // 8192  : z
#define S_DBL  36928      // 2304  : dbl (dt_raw | B | C)
#define S_DT   39232      // 8192  : dt
#define S_ST   47424      // 128   : mean/inv per row
#define SMEM1_FLOATS 47552
#define S_WO   0          // 8320  : out_w^T padded (128 x 65)  (reuses S_W)
#define S_XP   8320       // 4608  : x_proj_w^T (128 x 36)      (reuses S_W)
#define S_KT   0          // 4160  : k_w^T padded (64 x 65)     (reuses S_W)
#define S_VT   4160       // 4160  : v_w^T padded

__global__ void __launch_bounds__(512,1) k_mamba(
    const float* __restrict__ x,
    const float* __restrict__ ln1_g, const float* __restrict__ ln1_b,
    const float* __restrict__ in_proj_w,
    const float* __restrict__ conv_w, const float* __restrict__ conv_b,
    const float* __restrict__ x_proj_w,
    const float* __restrict__ dt_w,  const float* __restrict__ dt_b,
    const float* __restrict__ A_log, const float* __restrict__ D_ssm,
    const float* __restrict__ out_w,
    const float* __restrict__ k_w, const float* __restrict__ k_b,
    const float* __restrict__ v_w, const float* __restrict__ v_b)
{
    extern __shared__ float sm[];
    const int tid = threadIdx.x;
    const int seq = blockIdx.x;
    const int b = seq / NODES, n = seq % NODES;
    const size_t xbase = ((size_t)b*T_LEN)*NODES*DM + (size_t)n*DM;

    // ---- load raw x rows + in_proj^T (padded stride 257, conflict-free) ----
    for (int i = tid; i < T_LEN*DM; i += 512){
        int t = i >> 6, k = i & 63;
        sm[S_H + i] = x[xbase + (size_t)t*NODES*DM + k];
    }
    for (int i = tid; i < 256*64; i += 512){
        int c = i >> 6, k = i & 63;
        sm[S_W + k*257 + c] = in_proj_w[i];
    }
    __syncthreads();

    // ---- layernorm1 stats (warp per 4 rows) ----
    {
        int wid = tid >> 5, lane = tid & 31;
        #pragma unroll
        for (int r = 0; r < 4; r++){
            int t = wid*4 + r;
            float v0 = sm[S_H + t*64 + lane], v1 = sm[S_H + t*64 + lane + 32];
            float s = v0 + v1;
            #pragma unroll
            for (int o = 16; o; o >>= 1) s += __shfl_xor_sync(0xffffffffu, s, o);
            float m = s * (1.f/64.f);
            float d0 = v0 - m, d1 = v1 - m;
            float q = d0*d0 + d1*d1;
            #pragma unroll
            for (int o = 16; o; o >>= 1) q += __shfl_xor_sync(0xffffffffu, q, o);
            if (lane == 0){ sm[S_ST + t] = m; sm[S_ST + 64 + t] = rsqrtf(q*(1.f/64.f) + EPSV); }
        }
    }
    __syncthreads();
    for (int i = tid; i < T_LEN*DM; i += 512){
        int t = i >> 6, k = i & 63;
        sm[S_H + i] = (sm[S_H + i] - sm[S_ST + t]) * sm[S_ST + 64 + t] * ln1_g[k] + ln1_b[k];
    }
    __syncthreads();

    // ---- xz = hln @ in_proj^T : 256 out-channels x 64 timesteps ----
    {
        int c = tid & 255, th = tid >> 8;      // th in {0,1}, 32 timesteps each
        for (int t0 = th*32; t0 < th*32 + 32; t0 += 4){
            float a0 = 0.f, a1 = 0.f, a2 = 0.f, a3 = 0.f;
            #pragma unroll 8
            for (int k = 0; k < 64; k++){
                float w = sm[S_W + k*257 + c];
                a0 += sm[S_H + (t0+0)*64 + k] * w;
                a1 += sm[S_H + (t0+1)*64 + k] * w;
                a2 += sm[S_H + (t0+2)*64 + k] * w;
                a3 += sm[S_H + (t0+3)*64 + k] * w;
            }
            if (c < DI){
                sm[S_XC + (t0+0)*DI + c] = a0; sm[S_XC + (t0+1)*DI + c] = a1;
                sm[S_XC + (t0+2)*DI + c] = a2; sm[S_XC + (t0+3)*DI + c] = a3;
            } else {
                int cz = c - DI;
                sm[S_Z + (t0+0)*DI + cz] = a0; sm[S_Z + (t0+1)*DI + cz] = a1;
                sm[S_Z + (t0+2)*DI + cz] = a2; sm[S_Z + (t0+3)*DI + cz] = a3;
            }
        }
    }
    __syncthreads();

    // ---- conv(4-tap causal) + silu on threads 0..127; others stage out_w^T & x_proj^T ----
    if (tid < DI){
        int d = tid;
        float w0 = conv_w[d*4+0], w1 = conv_w[d*4+1], w2 = conv_w[d*4+2], w3 = conv_w[d*4+3];
        float cb = conv_b[d];
        float p3 = 0.f, p2 = 0.f, p1 = 0.f;
        for (int t = 0; t < T_LEN; t++){
            float cur = sm[S_XC + t*DI + d];
            float v = cb + w0*p3 + w1*p2 + w2*p1 + w3*cur;
            p3 = p2; p2 = p1; p1 = cur;
            sm[S_XC + t*DI + d] = siluf(v);
        }
    } else {
        for (int i = tid - DI; i < 64*DI; i += 512 - DI){
            int c = i >> 7, d = i & 127;
            sm[S_WO + d*65 + c] = out_w[i];
        }
        for (int i = tid - DI; i < 36*DI; i += 512 - DI){
            int r = i >> 7, d = i & 127;
            sm[S_XP + d*36 + r] = x_proj_w[i];
        }
    }
    __syncthreads();

    // ---- dbl = xc @ x_proj^T  (64 x 36) ----
    for (int i = tid; i < T_LEN*36; i += 512){
        int t = i / 36, r = i % 36;
        float a = 0.f;
        #pragma unroll 8
        for (int d = 0; d < DI; d++) a += sm[S_XC + t*DI + d] * sm[S_XP + d*36 + r];
        sm[S_DBL + t*36 + r] = a;
    }
    __syncthreads();

    // ---- dt = softplus(dt_raw @ dt_w^T + dt_b) ----
    for (int i = tid; i < T_LEN*DI; i += 512){
        int t = i >> 7, d = i & 127;
        float s = dt_b[d];
        #pragma unroll
        for (int r = 0; r < 4; r++) s += sm[S_DBL + t*36 + r] * dt_w[d*4 + r];
        sm[S_DT + i] = softplusf(s);
    }
    __syncthreads();

    // ---- selective scan: threads 0..255, 2 threads per channel (8 states each) ----
    if (tid < 256){
        int d = tid >> 1, half = tid & 1, s0 = half*8;
        float A[8], hs[8];
        #pragma unroll
        for (int s = 0; s < 8; s++){ A[s] = -__expf(A_log[d*DS + s0 + s]); hs[s] = 0.f; }
        float Dv = D_ssm[d];
        for (int t = 0; t < T_LEN; t++){
            float dt = sm[S_DT + t*DI + d];
            float xv = sm[S_XC + t*DI + d];
            float dx = dt * xv;
            float y = 0.f;
            #pragma unroll
            for (int s = 0; s < 8; s++){
                float dA = __expf(dt * A[s]);
                hs[s] = hs[s]*dA + dx * sm[S_DBL + t*36 + 4  + s0 + s];
                y    += hs[s] *       sm[S_DBL + t*36 + 20 + s0 + s];
            }
            y += __shfl_xor_sync(0xffffffffu, y, 1);
            if (half == 0){
                float yt = y + Dv*xv;
                yt *= siluf(sm[S_Z + t*DI + d]);
                sm[S_XC + t*DI + d] = yt;
            }
        }
    }
    __syncthreads();

    // ---- out proj + residual -> g_xt and smem; then stage k/v weights ----
    {
        int cc = tid & 63, tg = tid >> 6;   // tg 0..7, 8 timesteps each
        float acc[8];
        #pragma unroll
        for (int j = 0; j < 8; j++) acc[j] = 0.f;
        for (int d = 0; d < DI; d++){
            float w = sm[S_WO + d*65 + cc];
            #pragma unroll
            for (int j = 0; j < 8; j++) acc[j] += sm[S_XC + (tg*8 + j)*DI + d] * w;
        }
        __syncthreads();   // everyone done reading S_W region & S_XC
        #pragma unroll
        for (int j = 0; j < 8; j++){
            int t = tg*8 + j;
            float raw = x[xbase + (size_t)t*NODES*DM + cc];
            float o = raw + acc[j];
            g_xt[((size_t)seq*T_LEN + t)*DM + cc] = o;
            sm[S_H + t*64 + cc] = o;
        }
        for (int i = tid; i < 64*64; i += 512){
            int c = i >> 6, k = i & 63;
            sm[S_KT + k*65 + c] = k_w[i];
            sm[S_VT + k*65 + c] = v_w[i];
        }
    }
    __syncthreads();

    // ---- K,V projections (fused; xt rows already in smem) ----
    {
        int cc = tid & 63, tg = tid >> 6;
        float ak[8], av[8];
        #pragma unroll
        for (int j = 0; j < 8; j++){ ak[j] = 0.f; av[j] = 0.f; }
        for (int k = 0; k < 64; k++){
            float wk = sm[S_KT + k*65 + cc];
            float wv = sm[S_VT + k*65 + cc];
            #pragma unroll
            for (int j = 0; j < 8; j++){
                float h = sm[S_H + (tg*8 + j)*64 + k];
                ak[j] += h*wk; av[j] += h*wv;
            }
        }
        float kb = k_b[cc], vb = v_b[cc];
        #pragma unroll
        for (int j = 0; j < 8; j++){
            int t = tg*8 + j;
            size_t o = (((size_t)b*T_LEN + t)*NODES + n)*DM + cc;
            g_K[o] = ak[j] + kb;
            g_V[o] = av[j] + vb;
        }
    }
}

// ---------------- kernel 2: Q proj + neighbor attention + gate + LN2 ----------------
#define NPB     32
#define NCHUNK  11   // ceil(325/32)
#define A_QW   0      // 4160
#define A_OW   4160   // 4160
#define A_G1   8320   // 1088 (64 x 17)
#define A_QB   9408
#define A_OB   9472
#define A_G1B  9536
#define A_G2W  9552
#define A_WS   9568
#define WS_SZ  1248   // per-warp: xr 64 | Q 64 | og 64 | att 32 | Kn 512 | Vn 512
#define SMEM2_FLOATS (A_WS + 8*WS_SZ)   // 19552

__global__ void __launch_bounds__(256,2) k_attn(
    const int*   __restrict__ nbr,
    const float* __restrict__ q_w, const float* __restrict__ q_b,
    const float* __restrict__ o_w, const float* __restrict__ o_b,
    const float* __restrict__ g1_w, const float* __restrict__ g1_b,
    const float* __restrict__ g2_w, const float* __restrict__ g2_b,
    const float* __restrict__ ln2_g, const float* __restrict__ ln2_b,
    float* __restrict__ out)
{
    extern __shared__ float sm[];
    const int tid = threadIdx.x;
    const int chunk = blockIdx.x % NCHUNK;
    const int bt = blockIdx.x / NCHUNK;
    const int b = bt >> 6, t = bt & 63;

    for (int i = tid; i < 4096; i += 256){
        int c = i >> 6, k = i & 63;
        sm[A_QW + k*65 + c] = q_w[i];
        sm[A_OW + k*65 + c] = o_w[i];
    }
    for (int i = tid; i < 1024; i += 256){
        int r = i >> 6, k = i & 63;
        sm[A_G1 + k*17 + r] = g1_w[i];
    }
    if (tid < 64){ sm[A_QB + tid] = q_b[tid]; sm[A_OB + tid] = o_b[tid]; }
    if (tid < 16){ sm[A_G1B + tid] = g1_b[tid]; sm[A_G2W + tid] = g2_w[tid]; }
    __syncthreads();

    const int wid = tid >> 5, lane = tid & 31;
    float* W = sm + A_WS + wid*WS_SZ;
    const float g2b = g2_b[0];
    const float lg0 = ln2_g[lane], lg1 = ln2_g[lane + 32];
    const float lb0 = ln2_b[lane], lb1 = ln2_b[lane + 32];

    for (int ii = 0; ii < 4; ii++){
        int n = chunk*NPB + wid*4 + ii;
        if (n >= NODES) break;                    // uniform per warp
        __syncwarp();
        size_t xoff = (((size_t)b*NODES + n)*T_LEN + t)*DM;
        W[lane]      = g_xt[xoff + lane];
        W[lane + 32] = g_xt[xoff + lane + 32];
        __syncwarp();

        // Q projection
        {
            float a0 = sm[A_QB + lane], a1 = sm[A_QB + lane + 32];
            #pragma unroll 8
            for (int k = 0; k < 64; k++){
                float xv = W[k];
                a0 += xv * sm[A_QW + k*65 + lane];
                a1 += xv * sm[A_QW + k*65 + lane + 32];
            }
            W[64 + lane] = a0; W[64 + lane + 32] = a1;
        }

        // gather neighbor K/V rows (coalesced: (b,t,n,c) layout)
        #pragma unroll
        for (int j = 0; j < 8; j++){
            int nb = nbr[n*TOPK + j];
            size_t ko = (((size_t)b*T_LEN + t)*NODES + nb)*DM;
            W[224 + j*64 + lane]      = g_K[ko + lane];
            W[224 + j*64 + lane + 32] = g_K[ko + lane + 32];
            W[736 + j*64 + lane]      = g_V[ko + lane];
            W[736 + j*64 + lane + 32] = g_V[ko + lane + 32];
        }
        __syncwarp();

        // logits (lane = h*8 + j) + softmax over 8 neighbors
        {
            int h = lane >> 3, j = lane & 7;
            float lgt = 0.f;
            #pragma unroll
            for (int e = 0; e < 16; e++) lgt += W[64 + h*16 + e] * W[224 + j*64 + h*16 + e];
            lgt *= 0.25f;
            float mx = lgt;
            #pragma unroll
            for (int o = 4; o; o >>= 1) mx = fmaxf(mx, __shfl_xor_sync(0xffffffffu, mx, o));
            float ex = __expf(lgt - mx);
            float ss = ex;
            #pragma unroll
            for (int o = 4; o; o >>= 1) ss += __shfl_xor_sync(0xffffffffu, ss, o);
            W[192 + lane] = ex / ss;
        }
        __syncwarp();

        // weighted V
        {
            int c0 = lane, c1 = lane + 32;
            int h0 = c0 >> 4, h1 = c1 >> 4;
            float a0 = 0.f, a1 = 0.f;
            #pragma unroll
            for (int j = 0; j < 8; j++){
                a0 += W[192 + h0*8 + j] * W[736 + j*64 + c0];
                a1 += W[192 + h1*8 + j] * W[736 + j*64 + c1];
            }
            W[128 + c0] = a0; W[128 + c1] = a1;
        }
        __syncwarp();

        // o-proj, gate, blend, layernorm2
        float xg0 = sm[A_OB + lane], xg1 = sm[A_OB + lane + 32];
        #pragma unroll 8
        for (int k = 0; k < 64; k++){
            float ov = W[128 + k];
            xg0 += ov * sm[A_OW + k*65 + lane];
            xg1 += ov * sm[A_OW + k*65 + lane + 32];
        }
        float p = 0.f;
        if (lane < 16){
            float tg = sm[A_G1B + lane];
            #pragma unroll 8
            for (int k = 0; k < 64; k++) tg += W[k] * sm[A_G1 + k*17 + lane];
            float ge = 0.5f * tg * (1.f + erff(tg * 0.70710678118654752f));  // exact gelu
            p = ge * sm[A_G2W + lane];
        }
        #pragma unroll
        for (int o = 16; o; o >>= 1) p += __shfl_xor_sync(0xffffffffu, p, o);
        float g = 1.f / (1.f + __expf(-(p + g2b)));

        float x0 = W[lane], x1 = W[lane + 32];
        float o0 = x0 + g*(xg0 - x0);
        float o1 = x1 + g*(xg1 - x1);

        float s = o0 + o1;
        #pragma unroll
        for (int o = 16; o; o >>= 1) s += __shfl_xor_sync(0xffffffffu, s, o);
        float m = s * (1.f/64.f);
        float d0 = o0 - m, d1 = o1 - m;
        float q = d0*d0 + d1*d1;
        #pragma unroll
        for (int o = 16; o; o >>= 1) q += __shfl_xor_sync(0xffffffffu, q, o);
        float inv = rsqrtf(q*(1.f/64.f) + EPSV);

        size_t oo = (((size_t)b*T_LEN + t)*NODES + n)*DM;
        out[oo + lane]      = d0*inv*lg0 + lb0;
        out[oo + lane + 32] = d1*inv*lg1 + lb1;
    }
}

// ------------------------------ launch ------------------------------
extern "C" void kernel_launch(void* const* d_in, const int* in_sizes, int n_in,
                              void* d_out, int out_size)
{
    const float* x         = (const float*)d_in[0];
    const int*   nbr       = (const int*)  d_in[1];
    const float* ln1_g     = (const float*)d_in[2];
    const float* ln1_b     = (const float*)d_in[3];
    const float* in_proj_w = (const float*)d_in[4];
    const float* conv_w    = (const float*)d_in[5];
    const float* conv_b    = (const float*)d_in[6];
    const float* x_proj_w  = (const float*)d_in[7];
    const float* dt_w      = (const float*)d_in[8];
    const float* dt_b      = (const float*)d_in[9];
    const float* A_log     = (const float*)d_in[10];
    const float* D_ssm     = (const float*)d_in[11];
    const float* out_w     = (const float*)d_in[12];
    const float* q_w       = (const float*)d_in[13];
    const float* q_b       = (const float*)d_in[14];
    const float* k_w       = (const float*)d_in[15];
    const float* k_b       = (const float*)d_in[16];
    const float* v_w       = (const float*)d_in[17];
    const float* v_b       = (const float*)d_in[18];
    const float* o_w       = (const float*)d_in[19];
    const float* o_b       = (const float*)d_in[20];
    const float* g1_w      = (const float*)d_in[21];
    const float* g1_b      = (const float*)d_in[22];
    const float* g2_w      = (const float*)d_in[23];
    const float* g2_b      = (const float*)d_in[24];
    const float* ln2_g     = (const float*)d_in[25];
    const float* ln2_b     = (const float*)d_in[26];

    cudaFuncSetAttribute(k_mamba, cudaFuncAttributeMaxDynamicSharedMemorySize, SMEM1_FLOATS*4);
    cudaFuncSetAttribute(k_attn,  cudaFuncAttributeMaxDynamicSharedMemorySize, SMEM2_FLOATS*4);

    k_mamba<<<BN, 512, SMEM1_FLOATS*4>>>(x, ln1_g, ln1_b, in_proj_w, conv_w, conv_b,
                                         x_proj_w, dt_w, dt_b, A_log, D_ssm, out_w,
                                         k_w, k_b, v_w, v_b);
    k_attn<<<B_SZ*T_LEN*NCHUNK, 256, SMEM2_FLOATS*4>>>(nbr, q_w, q_b, o_w, o_b,
                                                       g1_w, g1_b, g2_w, g2_b,
                                                       ln2_g, ln2_b, (float*)d_out);
}